// round 4
// baseline (speedup 1.0000x reference)
#include <cuda_runtime.h>

// Problem constants (fixed by the dataset)
#define NA 250000
#define NB 500000
#define NG 50000
#define DD 64
#define EA 1000000
#define EG 500000

// Output layout (float offsets): [atom_ft | ft(NB x 320) | global_ft]
#define OFF_FT  (NA * DD)                 // 16,000,000
#define OFF_GL  (OFF_FT + NB * 320)       // 176,000,000

// Per-destination edge bins (atomic bump allocation). Degrees ~Poisson(2)/(1);
// capacities astronomically safe; clamped anyway.
#define CAP_A 48
#define CAP_G 32

// Counts are zero-initialized at module load; the reduce kernel re-zeros them
// after use, so every kernel_launch call sees zeros (deterministic per replay).
__device__ int g_cnt_a[NB];
__device__ int g_cnt_g[NB];
__device__ int g_bin_a[(long long)NB * CAP_A];
__device__ int g_bin_g[(long long)NB * CAP_G];

// ---------------------------------------------------------------------------
// Kernel 1: edge binning (latency-bound atomics) fused with the atom/global
// passthrough copies (bandwidth-bound streaming) so they overlap.
// ---------------------------------------------------------------------------
#define EDGE_BLOCKS (((EA + EG) + 255) / 256)          // 5860
#define COPY_BLOCKS ((NA * 16 + NG * 16) / 256)        // 18750

__global__ void __launch_bounds__(256)
scatter_copy_kernel(const int* __restrict__ a_src,
                    const int* __restrict__ a_dst,
                    const int* __restrict__ g_src,
                    const int* __restrict__ g_dst,
                    const float4* __restrict__ atom4,
                    const float4* __restrict__ glob4,
                    float4* __restrict__ out4) {
    int b = blockIdx.x;
    if (b < EDGE_BLOCKS) {
        int e = b * 256 + threadIdx.x;
        if (e < EA) {
            int s = a_src[e];
            int d = a_dst[e];
            int pos = atomicAdd(g_cnt_a + d, 1);
            if (pos < CAP_A) g_bin_a[(long long)d * CAP_A + pos] = s;
        } else {
            int eg = e - EA;
            if (eg < EG) {
                int s = g_src[eg];
                int d = g_dst[eg];
                int pos = atomicAdd(g_cnt_g + d, 1);
                if (pos < CAP_G) g_bin_g[(long long)d * CAP_G + pos] = s;
            }
        }
        return;
    }
    int i = (b - EDGE_BLOCKS) * 256 + threadIdx.x;
    if (i < NA * 16) {
        __stcs(out4 + i, __ldg(atom4 + i));        // pre-warms L2 with atom table
    } else {
        int j = i - NA * 16;
        __stcs(out4 + (OFF_GL / 4) + j, __ldg(glob4 + j));
    }
}

// ---------------------------------------------------------------------------
// Kernel 2: per-bond gather-reduce. 16 lanes per row, lane owns 4 features.
// ---------------------------------------------------------------------------
#define ACC(v)                                                     \
    do {                                                           \
        s.x += (v).x; s.y += (v).y; s.z += (v).z; s.w += (v).w;    \
        m.x = fmaxf(m.x, (v).x); m.y = fmaxf(m.y, (v).y);          \
        m.z = fmaxf(m.z, (v).z); m.w = fmaxf(m.w, (v).w);          \
    } while (0)

__device__ __forceinline__ void gather_reduce(const int* __restrict__ bin,
                                              const float4* __restrict__ tab,
                                              int deg, int lane,
                                              float4* __restrict__ o_mean,
                                              float4* __restrict__ o_max) {
    const float NINF = __int_as_float(0xFF800000);
    float4 s = make_float4(0.f, 0.f, 0.f, 0.f);
    float4 m = make_float4(NINF, NINF, NINF, NINF);

    #pragma unroll 1
    for (int j = 0; j < deg; j += 4) {
        int last = deg - 1;
        // Clamped indices: all 4 feature loads unconditional (MLP=4),
        // accumulation predicated on validity.
        int i0 = __ldg(bin + j);
        int i1 = __ldg(bin + (j + 1 <= last ? j + 1 : last));
        int i2 = __ldg(bin + (j + 2 <= last ? j + 2 : last));
        int i3 = __ldg(bin + (j + 3 <= last ? j + 3 : last));
        float4 v0 = __ldg(tab + (long long)i0 * 16 + lane);
        float4 v1 = __ldg(tab + (long long)i1 * 16 + lane);
        float4 v2 = __ldg(tab + (long long)i2 * 16 + lane);
        float4 v3 = __ldg(tab + (long long)i3 * 16 + lane);
        ACC(v0);
        if (j + 1 < deg) ACC(v1);
        if (j + 2 < deg) ACC(v2);
        if (j + 3 < deg) ACC(v3);
    }
    float inv = 1.0f / (float)(deg > 1 ? deg : 1);
    __stcs(o_mean, make_float4(s.x * inv, s.y * inv, s.z * inv, s.w * inv));
    __stcs(o_max, deg ? m : make_float4(0.f, 0.f, 0.f, 0.f));
}

__global__ void __launch_bounds__(256)
reduce_kernel(const float4* __restrict__ bond4,
              const float4* __restrict__ atom4,
              const float4* __restrict__ glob4,
              float4* __restrict__ out4) {
    // NB*16 == 8,000,000 is an exact multiple of 256: no tail, no divergence.
    int t    = blockIdx.x * 256 + threadIdx.x;
    int row  = t >> 4;
    int lane = t & 15;

    // Lane 0 of each 16-lane group reads both degrees and resets the counters
    // for the next replay (load+store same thread = ordered; each row is
    // touched by exactly one group). Broadcast via width-16 shuffle.
    int da = 0, dg = 0;
    if (lane == 0) {
        da = g_cnt_a[row];
        dg = g_cnt_g[row];
        g_cnt_a[row] = 0;
        g_cnt_g[row] = 0;
    }
    da = __shfl_sync(0xffffffffu, da, 0, 16);
    dg = __shfl_sync(0xffffffffu, dg, 0, 16);
    if (da > CAP_A) da = CAP_A;
    if (dg > CAP_G) dg = CAP_G;

    // Front-batch the independent loads: bond row + both first index batches.
    float4 bv = __ldcs(bond4 + (long long)row * 16 + lane);

    float4* __restrict__ orow = out4 + (OFF_FT / 4) + (long long)row * 80;
    __stcs(orow + lane, bv);

    gather_reduce(g_bin_a + (long long)row * CAP_A, atom4, da, lane,
                  orow + 16 + lane, orow + 32 + lane);
    gather_reduce(g_bin_g + (long long)row * CAP_G, glob4, dg, lane,
                  orow + 48 + lane, orow + 64 + lane);
}

extern "C" void kernel_launch(void* const* d_in, const int* in_sizes, int n_in,
                              void* d_out, int out_size) {
    const float4* atom4   = (const float4*)d_in[0];
    const float4* bond4   = (const float4*)d_in[1];
    const float4* glob4   = (const float4*)d_in[2];
    const int*    a2b_src = (const int*)d_in[3];
    const int*    a2b_dst = (const int*)d_in[4];
    const int*    g2b_src = (const int*)d_in[5];
    const int*    g2b_dst = (const int*)d_in[6];
    float* out = (float*)d_out;

    scatter_copy_kernel<<<EDGE_BLOCKS + COPY_BLOCKS, 256>>>(
        a2b_src, a2b_dst, g2b_src, g2b_dst, atom4, glob4, (float4*)out);

    int reduce_blocks = (int)(((long long)NB * 16) / 256);   // 31250
    reduce_kernel<<<reduce_blocks, 256>>>(bond4, atom4, glob4, (float4*)out);
}

// round 5
// speedup vs baseline: 1.9057x; 1.9057x over previous
#include <cuda_runtime.h>

// Problem constants (fixed by the dataset)
#define NA 250000
#define NB 500000
#define NG 50000
#define DD 64
#define EA 1000000
#define EG 500000

// Output layout (float offsets): [atom_ft | ft(NB x 320) | global_ft]
#define OFF_FT  (NA * DD)                 // 16,000,000
#define OFF_GL  (OFF_FT + NB * 320)       // 176,000,000

// Per-destination edge bins (atomic bump allocation). Degrees ~Poisson(2)/(1);
// capacities astronomically safe; clamped anyway. Bin contents are only ever
// valid src indices (or the zero-init value 0), so stale slots are always
// in-range -> speculative loads are safe.
#define CAP_A 48
#define CAP_G 32

__device__ int g_cnt_a[NB];
__device__ int g_cnt_g[NB];
__device__ int g_bin_a[(long long)NB * CAP_A];
__device__ int g_bin_g[(long long)NB * CAP_G];

__global__ void __launch_bounds__(256)
zero_cnt_kernel() {
    int i = blockIdx.x * blockDim.x + threadIdx.x;
    if (i < NB) { g_cnt_a[i] = 0; g_cnt_g[i] = 0; }
}

// Both edge sets in one launch (latency-bound spread atomics).
__global__ void __launch_bounds__(256)
scatter_kernel(const int* __restrict__ a_src,
               const int* __restrict__ a_dst,
               const int* __restrict__ g_src,
               const int* __restrict__ g_dst) {
    int e = blockIdx.x * blockDim.x + threadIdx.x;
    if (e < EA) {
        int s = a_src[e];
        int d = a_dst[e];
        int pos = atomicAdd(g_cnt_a + d, 1);
        if (pos < CAP_A) g_bin_a[(long long)d * CAP_A + pos] = s;
    } else {
        int eg = e - EA;
        if (eg < EG) {
            int s = g_src[eg];
            int d = g_dst[eg];
            int pos = atomicAdd(g_cnt_g + d, 1);
            if (pos < CAP_G) g_bin_g[(long long)d * CAP_G + pos] = s;
        }
    }
}

#define ACCA(v)                                                         \
    do {                                                                \
        sa.x += (v).x; sa.y += (v).y; sa.z += (v).z; sa.w += (v).w;     \
        ma.x = fmaxf(ma.x, (v).x); ma.y = fmaxf(ma.y, (v).y);           \
        ma.z = fmaxf(ma.z, (v).z); ma.w = fmaxf(ma.w, (v).w);           \
    } while (0)
#define ACCG(v)                                                         \
    do {                                                                \
        sg.x += (v).x; sg.y += (v).y; sg.z += (v).z; sg.w += (v).w;     \
        mg.x = fmaxf(mg.x, (v).x); mg.y = fmaxf(mg.y, (v).y);           \
        mg.z = fmaxf(mg.z, (v).z); mg.w = fmaxf(mg.w, (v).w);           \
    } while (0)

// Fused: passthrough copies as leading blocks (free + pre-warm L2),
// then per-bond gather-reduce with interleaved A/G first batches.
#define COPY_BLOCKS ((NA * 16 + NG * 16) / 256)   // 18750
__global__ void __launch_bounds__(256)
fused_kernel(const float4* __restrict__ bond4,
             const float4* __restrict__ atom4,
             const float4* __restrict__ glob4,
             float4* __restrict__ out4) {
    int b = blockIdx.x;
    if (b < COPY_BLOCKS) {
        int i = b * 256 + threadIdx.x;
        if (i < NA * 16) {
            __stcs(out4 + i, __ldg(atom4 + i));   // pre-warms L2 with atom table
        } else {
            int j = i - NA * 16;
            __stcs(out4 + (OFF_GL / 4) + j, __ldg(glob4 + j));
        }
        return;
    }

    // NB*16 == 8,000,000 is an exact multiple of 256: no tail, no divergence.
    long long t = (long long)(b - COPY_BLOCKS) * 256 + threadIdx.x;
    int row  = (int)(t >> 4);
    int lane = (int)(t & 15);

    // Uniform broadcast loads: all 16 lanes read the same counter word.
    int da = g_cnt_a[row]; if (da > CAP_A) da = CAP_A;
    int dg = g_cnt_g[row]; if (dg > CAP_G) dg = CAP_G;

    const int4* __restrict__ binA = (const int4*)(g_bin_a + (long long)row * CAP_A);
    const int4* __restrict__ binG = (const int4*)(g_bin_g + (long long)row * CAP_G);

    // ---- front-batched independent loads: bond row + both index vectors ----
    float4 bv = __ldcs(bond4 + (long long)row * 16 + lane);
    int4 ia = __ldg(binA);
    int4 ig = __ldg(binG);

    // 8 feature loads in flight (indices may be stale but always in-range)
    float4 a0 = __ldg(atom4 + (long long)ia.x * 16 + lane);
    float4 a1 = __ldg(atom4 + (long long)ia.y * 16 + lane);
    float4 a2 = __ldg(atom4 + (long long)ia.z * 16 + lane);
    float4 a3 = __ldg(atom4 + (long long)ia.w * 16 + lane);
    float4 g0 = __ldg(glob4 + (long long)ig.x * 16 + lane);
    float4 g1 = __ldg(glob4 + (long long)ig.y * 16 + lane);
    float4 g2 = __ldg(glob4 + (long long)ig.z * 16 + lane);
    float4 g3 = __ldg(glob4 + (long long)ig.w * 16 + lane);

    float4* __restrict__ orow = out4 + (OFF_FT / 4) + (long long)row * 80;
    __stcs(orow + lane, bv);                       // bond passthrough

    const float NINF = __int_as_float(0xFF800000);
    float4 sa = make_float4(0.f, 0.f, 0.f, 0.f);
    float4 ma = make_float4(NINF, NINF, NINF, NINF);
    float4 sg = make_float4(0.f, 0.f, 0.f, 0.f);
    float4 mg = make_float4(NINF, NINF, NINF, NINF);

    if (da > 0) ACCA(a0);
    if (da > 1) ACCA(a1);
    if (da > 2) ACCA(a2);
    if (da > 3) ACCA(a3);
    if (dg > 0) ACCG(g0);
    if (dg > 1) ACCG(g1);
    if (dg > 2) ACCG(g2);
    if (dg > 3) ACCG(g3);

    // ---- rare tails (deg > 4): ~5% of A rows, ~0.4% of G rows ----
    #pragma unroll 1
    for (int j = 4; j < da; j += 4) {
        int4 ix = __ldg(binA + (j >> 2));
        float4 v0 = __ldg(atom4 + (long long)ix.x * 16 + lane);
        float4 v1 = __ldg(atom4 + (long long)ix.y * 16 + lane);
        float4 v2 = __ldg(atom4 + (long long)ix.z * 16 + lane);
        float4 v3 = __ldg(atom4 + (long long)ix.w * 16 + lane);
        ACCA(v0);
        if (j + 1 < da) ACCA(v1);
        if (j + 2 < da) ACCA(v2);
        if (j + 3 < da) ACCA(v3);
    }
    #pragma unroll 1
    for (int j = 4; j < dg; j += 4) {
        int4 ix = __ldg(binG + (j >> 2));
        float4 v0 = __ldg(glob4 + (long long)ix.x * 16 + lane);
        float4 v1 = __ldg(glob4 + (long long)ix.y * 16 + lane);
        float4 v2 = __ldg(glob4 + (long long)ix.z * 16 + lane);
        float4 v3 = __ldg(glob4 + (long long)ix.w * 16 + lane);
        ACCG(v0);
        if (j + 1 < dg) ACCG(v1);
        if (j + 2 < dg) ACCG(v2);
        if (j + 3 < dg) ACCG(v3);
    }

    float inva = 1.0f / (float)(da > 1 ? da : 1);
    float invg = 1.0f / (float)(dg > 1 ? dg : 1);
    __stcs(orow + 16 + lane, make_float4(sa.x * inva, sa.y * inva,
                                         sa.z * inva, sa.w * inva));
    __stcs(orow + 32 + lane, da ? ma : make_float4(0.f, 0.f, 0.f, 0.f));
    __stcs(orow + 48 + lane, make_float4(sg.x * invg, sg.y * invg,
                                         sg.z * invg, sg.w * invg));
    __stcs(orow + 64 + lane, dg ? mg : make_float4(0.f, 0.f, 0.f, 0.f));
}

extern "C" void kernel_launch(void* const* d_in, const int* in_sizes, int n_in,
                              void* d_out, int out_size) {
    const float4* atom4   = (const float4*)d_in[0];
    const float4* bond4   = (const float4*)d_in[1];
    const float4* glob4   = (const float4*)d_in[2];
    const int*    a2b_src = (const int*)d_in[3];
    const int*    a2b_dst = (const int*)d_in[4];
    const int*    g2b_src = (const int*)d_in[5];
    const int*    g2b_dst = (const int*)d_in[6];
    float* out = (float*)d_out;

    zero_cnt_kernel<<<(NB + 255) / 256, 256>>>();

    scatter_kernel<<<(EA + EG + 255) / 256, 256>>>(a2b_src, a2b_dst,
                                                   g2b_src, g2b_dst);

    int reduce_blocks = (int)(((long long)NB * 16) / 256);   // 31250
    fused_kernel<<<COPY_BLOCKS + reduce_blocks, 256>>>(bond4, atom4, glob4,
                                                       (float4*)out);
}